// round 7
// baseline (speedup 1.0000x reference)
#include <cuda_runtime.h>

#define NN 400      // nodes
#define FD 240      // node feature dim
#define CD 32       // stack channels
#define LD 1440     // labels
#define NIN 304     // F + 2C
#define NKS 8       // node k-split count (304 = 8*38)
#define NKL 38      // node k-slice length
#define DKS 4       // dense k-split count (240 = 4*60)

// ---------------- scratch ----------------
__device__ float g_U[NN * CD];
__device__ float g_V[NN * CD];
__device__ float g_aggi[NN * CD];
__device__ float g_aggj[NN * CD];
__device__ float g_e1[NN * NN];
__device__ float g_p1[NKS * NN * FD];   // layer-1 x_out k-split partials
__device__ float g_p2[NKS * NN * FD];   // layer-2 x_out k-split partials
__device__ float g_pd[DKS * NN * LD];   // dense k-split partials

__device__ __forceinline__ float sum_parts(const float* base, int off)
{
    float s = 0.f;
#pragma unroll
    for (int z = 0; z < NKS; z++) s += base[z * NN * FD + off];
    return s;
}

// ---------------- proj: U/V = x @ sw(+sb). LAYER2 reads x1 = sum of partials ----
template <bool LAYER2>
__global__ void __launch_bounds__(256)
proj_kernel(const float* __restrict__ x_in,
            const float* __restrict__ sw,
            const float* __restrict__ sb)
{
    __shared__ float xs[FD];
    __shared__ float red[4][64];
    int i = blockIdx.x;
    for (int f = threadIdx.x; f < FD; f += 256)
        xs[f] = LAYER2 ? sum_parts(g_p1, i * FD + f) : x_in[i * FD + f];
    __syncthreads();

    int ks  = threadIdx.x >> 6;
    int c64 = threadIdx.x & 63;
    int c   = c64 & 31;
    const float* w = sw + ((c64 < 32) ? 0 : FD * CD) + c;
    float acc = 0.f;
    int f0 = ks * 60;
#pragma unroll 15
    for (int f = f0; f < f0 + 60; f++) acc = fmaf(xs[f], w[f * CD], acc);
    red[ks][c64] = acc;
    __syncthreads();
    if (threadIdx.x < 64) {
        int t = threadIdx.x;
        float s = red[0][t] + red[1][t] + red[2][t] + red[3][t];
        if (t < 32) g_U[i * CD + t] = s + sb[t];
        else        g_V[i * CD + c] = s;
    }
}

// ---------------- fused att+agg: block per node n -------------------------------
// Phase A (thread = partner t): compute BOTH gates the block needs —
//   gI[t] = sigmoid(att_i logit of pair (n,t))   [stack(n,t)]
//   gJ[t] = sigmoid(att_j logit of pair (t,n))   [stack(t,n)]
// plus layer-1 e_out row n. e/a rows+cols staged to shared for phase B.
// Phase B (13 warps, lane = channel): aggregate agg_i[n], agg_j[n].
template <bool WRITE_E, bool USE_E1>
__global__ void __launch_bounds__(416, 2)
attagg_kernel(const float* __restrict__ a, const float* __restrict__ e_in,
              const float* __restrict__ sw,
              const float* __restrict__ aiw, const float* __restrict__ aib,
              const float* __restrict__ ajw, const float* __restrict__ ajb,
              const float* __restrict__ ew,  const float* __restrict__ eb)
{
    const float* e = USE_E1 ? g_e1 : e_in;
    __shared__ float4 sUn[8], sVn[8], scv[8], sdv[8], swi4[8], swj4[8], swe4[8];
    __shared__ float gI[NN], gJ[NN];
    __shared__ float sEr[NN], sEc[NN], sAr[NN], sAc[NN];
    __shared__ float si[13][CD], sj[13][CD];
    int n = blockIdx.x;
    if (threadIdx.x < 8) {
        int t = threadIdx.x;
        sUn[t]  = ((const float4*)(g_U + n * CD))[t];
        sVn[t]  = ((const float4*)(g_V + n * CD))[t];
        scv[t]  = ((const float4*)(sw + 480 * CD))[t];
        sdv[t]  = ((const float4*)(sw + 481 * CD))[t];
        swi4[t] = ((const float4*)aiw)[t];
        swj4[t] = ((const float4*)ajw)[t];
        swe4[t] = WRITE_E ? ((const float4*)ew)[t] : make_float4(0.f, 0.f, 0.f, 0.f);
    }
    __syncthreads();

    int t = threadIdx.x;
    if (t < NN) {
        float ent = e[n * NN + t];
        float etn = e[t * NN + n];
        float ant = a[n * NN + t];
        float atn = a[t * NN + n];
        sEr[t] = ent; sEc[t] = etn; sAr[t] = ant; sAc[t] = atn;
        const float4* vt = (const float4*)(g_V + t * CD);
        const float4* ut = (const float4*)(g_U + t * CD);
        float d1 = 0.f, d2 = 0.f, d3 = 0.f;
#pragma unroll
        for (int cc = 0; cc < 8; cc++) {
            float4 v  = vt[cc],  u  = ut[cc];
            float4 un = sUn[cc], vn = sVn[cc];
            float4 c4 = scv[cc], dd = sdv[cc];
            float4 wi = swi4[cc], wj = swj4[cc], we = swe4[cc];
            float sr, sc;
            sr = fmaxf(fmaf(ent, c4.x, fmaf(etn, dd.x, un.x + v.x)), 0.f) * ant;
            sc = fmaxf(fmaf(etn, c4.x, fmaf(ent, dd.x, u.x + vn.x)), 0.f) * atn;
            d1 = fmaf(sr, wi.x, d1); d2 = fmaf(sc, wj.x, d2); if (WRITE_E) d3 = fmaf(sr, we.x, d3);
            sr = fmaxf(fmaf(ent, c4.y, fmaf(etn, dd.y, un.y + v.y)), 0.f) * ant;
            sc = fmaxf(fmaf(etn, c4.y, fmaf(ent, dd.y, u.y + vn.y)), 0.f) * atn;
            d1 = fmaf(sr, wi.y, d1); d2 = fmaf(sc, wj.y, d2); if (WRITE_E) d3 = fmaf(sr, we.y, d3);
            sr = fmaxf(fmaf(ent, c4.z, fmaf(etn, dd.z, un.z + v.z)), 0.f) * ant;
            sc = fmaxf(fmaf(etn, c4.z, fmaf(ent, dd.z, u.z + vn.z)), 0.f) * atn;
            d1 = fmaf(sr, wi.z, d1); d2 = fmaf(sc, wj.z, d2); if (WRITE_E) d3 = fmaf(sr, we.z, d3);
            sr = fmaxf(fmaf(ent, c4.w, fmaf(etn, dd.w, un.w + v.w)), 0.f) * ant;
            sc = fmaxf(fmaf(etn, c4.w, fmaf(ent, dd.w, u.w + vn.w)), 0.f) * atn;
            d1 = fmaf(sr, wi.w, d1); d2 = fmaf(sc, wj.w, d2); if (WRITE_E) d3 = fmaf(sr, we.w, d3);
        }
        gI[t] = 1.f / (1.f + __expf(-(d1 + aib[0])));
        gJ[t] = 1.f / (1.f + __expf(-(d2 + ajb[0])));
        if (WRITE_E) g_e1[n * NN + t] = d3 + eb[0];
    }
    __syncthreads();

    // phase B
    int lane = t & 31;
    int warp = t >> 5;   // 0..12
    float cvc = ((const float*)scv)[lane];
    float dvc = ((const float*)sdv)[lane];
    float Unc = ((const float*)sUn)[lane];
    float Vnc = ((const float*)sVn)[lane];

    float acc_i = 0.f, acc_j = 0.f;
#pragma unroll 2
    for (int m = warp; m < NN; m += 13) {
        float Um  = g_U[m * CD + lane];
        float Vm  = g_V[m * CD + lane];
        float enm = sEr[m], emn = sEc[m];
        float anm = sAr[m], amn = sAc[m];
        float srow = fmaxf(fmaf(enm, cvc, fmaf(emn, dvc, Unc + Vm)), 0.f) * anm;
        float scol = fmaxf(fmaf(emn, cvc, fmaf(enm, dvc, Um + Vnc)), 0.f) * amn;
        acc_i = fmaf(gI[m], srow, acc_i);
        acc_j = fmaf(gJ[m], scol, acc_j);
    }
    si[warp][lane] = acc_i;
    sj[warp][lane] = acc_j;
    __syncthreads();
    if (t < CD) {
        float ti = 0.f, tj = 0.f;
#pragma unroll
        for (int w = 0; w < 13; w++) { ti += si[w][t]; tj += sj[w][t]; }
        g_aggi[n * CD + t] = ti;
        g_aggj[n * CD + t] = tj;
    }
}

// ---------------- node model partials: k-split x8, TIN=8, regs unlocked ---------
// grid (50, 8), block 240, launch_bounds(240,4) -> 68-reg cap so ptxas can
// front-batch the 38 weight LDGs (high MLP).
#define TIN 8
template <int LAYER>
__global__ void __launch_bounds__(240, 4)
node_part(const float* __restrict__ x_in,
          const float* __restrict__ nw,
          const float* __restrict__ nb)
{
    __shared__ __align__(16) float s8[NKL][TIN];
    int z  = blockIdx.y;
    int k0 = z * NKL;
    int i0 = blockIdx.x * TIN;
    float* po = (LAYER == 1 ? g_p1 : g_p2) + z * NN * FD;

    for (int idx = threadIdx.x; idx < NKL * TIN; idx += FD) {
        int k = idx >> 3, r = idx & 7;
        int gk = k0 + k;
        int node = i0 + r;
        float v;
        if (gk < FD) {
            if (LAYER == 1) v = x_in[node * FD + gk];
            else            v = sum_parts(g_p1, node * FD + gk);
        } else if (gk < FD + CD) {
            v = g_aggi[node * CD + (gk - FD)];
        } else {
            v = g_aggj[node * CD + (gk - FD - CD)];
        }
        s8[k][r] = v;
    }
    __syncthreads();

    int o = threadIdx.x;
    float b = (z == 0) ? nb[o] : 0.f;
    float acc[TIN];
#pragma unroll
    for (int r = 0; r < TIN; r++) acc[r] = b;
    const float* wp = nw + k0 * FD + o;
#pragma unroll
    for (int kk = 0; kk < NKL; kk++) {
        float w   = wp[kk * FD];
        float4 a0 = *(const float4*)&s8[kk][0];
        float4 a1 = *(const float4*)&s8[kk][4];
        acc[0] = fmaf(a0.x, w, acc[0]);
        acc[1] = fmaf(a0.y, w, acc[1]);
        acc[2] = fmaf(a0.z, w, acc[2]);
        acc[3] = fmaf(a0.w, w, acc[3]);
        acc[4] = fmaf(a1.x, w, acc[4]);
        acc[5] = fmaf(a1.y, w, acc[5]);
        acc[6] = fmaf(a1.z, w, acc[6]);
        acc[7] = fmaf(a1.w, w, acc[7]);
    }
#pragma unroll
    for (int r = 0; r < TIN; r++) po[(i0 + r) * FD + o] = acc[r];
}

// ---------------- dense partials: 16 rows/thread, k-split x4 (60 f each) --------
#define TID 16
__global__ void __launch_bounds__(288, 2)
dense_part(const float* __restrict__ dw,
           const float* __restrict__ db)
{
    __shared__ __align__(16) float xs[60][20];   // [f][row], pad 20
    int z  = blockIdx.z;
    int f0 = z * 60;
    int i0 = blockIdx.y * TID;
    int o  = blockIdx.x * 288 + threadIdx.x;
    float* po = g_pd + z * NN * LD;

    for (int idx = threadIdx.x; idx < 60 * TID; idx += 288) {
        int r = idx / 60, f = idx % 60;
        xs[f][r] = sum_parts(g_p2, (i0 + r) * FD + f0 + f);
    }
    __syncthreads();

    float b = (z == 0) ? db[o] : 0.f;
    float acc[TID];
#pragma unroll
    for (int r = 0; r < TID; r++) acc[r] = b;
    const float* wp = dw + f0 * LD + o;
#pragma unroll 5
    for (int f = 0; f < 60; f++) {
        float w   = wp[f * LD];
        float4 a0 = *(const float4*)&xs[f][0];
        float4 a1 = *(const float4*)&xs[f][4];
        float4 a2 = *(const float4*)&xs[f][8];
        float4 a3 = *(const float4*)&xs[f][12];
        acc[0]  = fmaf(a0.x, w, acc[0]);   acc[1]  = fmaf(a0.y, w, acc[1]);
        acc[2]  = fmaf(a0.z, w, acc[2]);   acc[3]  = fmaf(a0.w, w, acc[3]);
        acc[4]  = fmaf(a1.x, w, acc[4]);   acc[5]  = fmaf(a1.y, w, acc[5]);
        acc[6]  = fmaf(a1.z, w, acc[6]);   acc[7]  = fmaf(a1.w, w, acc[7]);
        acc[8]  = fmaf(a2.x, w, acc[8]);   acc[9]  = fmaf(a2.y, w, acc[9]);
        acc[10] = fmaf(a2.z, w, acc[10]);  acc[11] = fmaf(a2.w, w, acc[11]);
        acc[12] = fmaf(a3.x, w, acc[12]);  acc[13] = fmaf(a3.y, w, acc[13]);
        acc[14] = fmaf(a3.z, w, acc[14]);  acc[15] = fmaf(a3.w, w, acc[15]);
    }
#pragma unroll
    for (int r = 0; r < TID; r++) po[(i0 + r) * LD + o] = acc[r];
}

// ---------------- dense reduce: out = sum of 4 partials (bias in partial 0) -----
__global__ void __launch_bounds__(256)
dense_reduce(float* __restrict__ out)
{
    int i = blockIdx.x * 256 + threadIdx.x;
    const int N4 = NN * LD / 4;
    if (i >= N4) return;
    float4 s = ((const float4*)g_pd)[i];
#pragma unroll
    for (int z = 1; z < DKS; z++) {
        float4 p = ((const float4*)(g_pd + z * NN * LD))[i];
        s.x += p.x; s.y += p.y; s.z += p.z; s.w += p.w;
    }
    ((float4*)out)[i] = s;
}

// ---------------- launch --------------------------------------------------------
extern "C" void kernel_launch(void* const* d_in, const int* in_sizes, int n_in,
                              void* d_out, int out_size)
{
    const float* x  = (const float*)d_in[0];
    const float* a  = (const float*)d_in[1];
    const float* e  = (const float*)d_in[2];
    const float* c1_sw  = (const float*)d_in[3];
    const float* c1_sb  = (const float*)d_in[4];
    const float* c1_aiw = (const float*)d_in[5];
    const float* c1_aib = (const float*)d_in[6];
    const float* c1_ajw = (const float*)d_in[7];
    const float* c1_ajb = (const float*)d_in[8];
    const float* c1_nw  = (const float*)d_in[9];
    const float* c1_nb  = (const float*)d_in[10];
    const float* c1_ew  = (const float*)d_in[11];
    const float* c1_eb  = (const float*)d_in[12];
    const float* c2_sw  = (const float*)d_in[13];
    const float* c2_sb  = (const float*)d_in[14];
    const float* c2_aiw = (const float*)d_in[15];
    const float* c2_aib = (const float*)d_in[16];
    const float* c2_ajw = (const float*)d_in[17];
    const float* c2_ajb = (const float*)d_in[18];
    const float* c2_nw  = (const float*)d_in[19];
    const float* c2_nb  = (const float*)d_in[20];
    const float* c2_ew  = (const float*)d_in[21];
    const float* c2_eb  = (const float*)d_in[22];
    const float* dw = (const float*)d_in[23];
    const float* db = (const float*)d_in[24];
    float* out = (float*)d_out;

    // ---- layer 1 ----
    proj_kernel<false><<<NN, 256>>>(x, c1_sw, c1_sb);
    attagg_kernel<true, false><<<NN, 416>>>(a, e, c1_sw,
                                            c1_aiw, c1_aib, c1_ajw, c1_ajb,
                                            c1_ew, c1_eb);
    node_part<1><<<dim3(NN / TIN, NKS), FD>>>(x, c1_nw, c1_nb);

    // ---- layer 2 (layer-2 e_out is dead) ----
    proj_kernel<true><<<NN, 256>>>(x, c2_sw, c2_sb);
    attagg_kernel<false, true><<<NN, 416>>>(a, e, c2_sw,
                                            c2_aiw, c2_aib, c2_ajw, c2_ajb,
                                            c2_ew, c2_eb);
    node_part<2><<<dim3(NN / TIN, NKS), FD>>>(x, c2_nw, c2_nb);

    // ---- final dense ----
    dense_part<<<dim3(LD / 288, NN / TID, DKS), 288>>>(dw, db);
    dense_reduce<<<(NN * LD / 4 + 255) / 256, 256>>>(out);
}